// round 1
// baseline (speedup 1.0000x reference)
#include <cuda_runtime.h>
#include <cstdint>

// BilateralFilter: x [B=2, C=3, H=384, W=384] fp32, ksize=9 (sigma = 1.7),
// reflect padding (no edge repeat).
//
// Math: out = sum_i exp(-(d_i^2)/(2s^2)) * ws_i * p_i / sum_i exp(...) * ws_i
// Both normalizations in the reference cancel in the ratio, and
// wd*ws = exp(-(d^2 + ry^2 + rx^2)/(2 s^2)), so per tap:
//   arg = C*d^2 + C*(ry^2+rx^2),  C = -1/(2 s^2 ln 2),  e = exp2(arg)

#define KSIZE 9
#define RAD   4
#define TILE  32
#define HALO  (TILE + 2*RAD)   // 40
#define H     384
#define W     384
#define NCH   6                // B*C = 2*3

__device__ __forceinline__ float ex2f(float x) {
    float y;
    asm("ex2.approx.ftz.f32 %0, %1;" : "=f"(y) : "f"(x));
    return y;
}

__device__ __forceinline__ int reflect_idx(int i, int n) {
    // pad (=4) < n, single reflection suffices. numpy 'reflect' (no edge repeat)
    if (i < 0)  i = -i;
    if (i >= n) i = 2 * n - 2 - i;
    return i;
}

__global__ __launch_bounds__(TILE * TILE)
void bilateral_kernel(const float* __restrict__ x, float* __restrict__ out) {
    __shared__ float s[HALO][HALO];

    const int ch = blockIdx.z;                   // 0..5
    const int bx = blockIdx.x * TILE;
    const int by = blockIdx.y * TILE;
    const float* __restrict__ xin = x + (size_t)ch * H * W;

    const int tx = threadIdx.x;
    const int ty = threadIdx.y;
    const int tid = ty * TILE + tx;

    // Cooperative load of 40x40 tile with reflect indexing (1600 elems / 1024 thr)
    #pragma unroll
    for (int i = tid; i < HALO * HALO; i += TILE * TILE) {
        const int ly = i / HALO;
        const int lx = i - ly * HALO;
        const int gy = reflect_idx(by + ly - RAD, H);
        const int gx = reflect_idx(bx + lx - RAD, W);
        s[ly][lx] = xin[gy * W + gx];
    }
    __syncthreads();

    // sigma = 0.3*((9-1)/2 - 1) + 0.8 = 1.7
    constexpr float SIGMA = 1.7f;
    constexpr float LN2   = 0.69314718055994530942f;
    constexpr float Cc    = -1.0f / (2.0f * SIGMA * SIGMA * LN2);  // exp2 domain

    const float ctr = s[ty + RAD][tx + RAD];
    const float cC  = ctr * Cc;   // hoist: d*C = p*C - ctr*C

    float sw  = 0.0f;
    float swp = 0.0f;

    #pragma unroll
    for (int dy = 0; dy < KSIZE; dy++) {
        const float ry2 = (float)((dy - RAD) * (dy - RAD));
        #pragma unroll
        for (int dx = 0; dx < KSIZE; dx++) {
            const float rx2  = (float)((dx - RAD) * (dx - RAD));
            const float base = Cc * (ry2 + rx2);          // compile-time const
            const float p  = s[ty + dy][tx + dx];
            const float d  = p - ctr;
            const float dC = fmaf(p, Cc, -cC);            // d * C
            const float arg = fmaf(dC, d, base);          // C*d^2 + base
            const float e   = ex2f(arg);
            sw  += e;
            swp  = fmaf(e, p, swp);
        }
    }

    const float r = __fdividef(swp, sw);
    out[(size_t)ch * H * W + (by + ty) * W + (bx + tx)] = r;
}

extern "C" void kernel_launch(void* const* d_in, const int* in_sizes, int n_in,
                              void* d_out, int out_size) {
    const float* x = (const float*)d_in[0];
    float* out = (float*)d_out;
    (void)in_sizes; (void)n_in; (void)out_size;

    dim3 block(TILE, TILE, 1);
    dim3 grid(W / TILE, H / TILE, NCH);   // 12 x 12 x 6
    bilateral_kernel<<<grid, block>>>(x, out);
}